// round 3
// baseline (speedup 1.0000x reference)
#include <cuda_runtime.h>

#define EPSV 1e-10f
#define BB 32
#define TT 512
#define NN 128

// Scratch (static device globals; no allocation).
__device__ float g_trans[NN * NN];   // trans_norm[prev][next]
__device__ float g_transT[NN * NN];  // [k][m] = trans_norm[m][k]
__device__ float g_prior[NN];        // normalized prior (linear)
__device__ float g_E[BB * TT * NN];  // exp(log_emission)
__device__ float g_W[BB * TT * NN];  // linear trellis w_t (scale pinned per step)
__device__ float g_V[BB * TT * NN];  // vh_t = (T^T w_{t-1}) / pin

// ---------- packed f32x2 helpers ----------
__device__ __forceinline__ unsigned long long fma2(unsigned long long a,
                                                   unsigned long long b,
                                                   unsigned long long c) {
    unsigned long long d;
    asm("fma.rn.f32x2 %0, %1, %2, %3;" : "=l"(d) : "l"(a), "l"(b), "l"(c));
    return d;
}
__device__ __forceinline__ float2 unpack2(unsigned long long v) {
    float2 r;
    asm("mov.b64 {%0, %1}, %2;" : "=f"(r.x), "=f"(r.y) : "l"(v));
    return r;
}
__device__ __forceinline__ unsigned long long pack2(float lo, float hi) {
    unsigned long long v;
    asm("mov.b64 %0, {%1, %2};" : "=l"(v) : "f"(lo), "f"(hi));
    return v;
}

// exact power-of-2 reciprocal of positive s (ALU pipe only, no MUFU):
// s = m*2^e with m in [1,2)  ->  returns 2^-e
__device__ __forceinline__ float inv_pin_of(float s) {
    unsigned u = __float_as_uint(s);
    unsigned E = u >> 23;  // s > 0 so sign bit is 0
    if (E == 0u || E >= 254u) return 1.0f;  // denormal/overflow guard
    return __uint_as_float((254u - E) << 23);
}

__device__ __forceinline__ float blk_sum128(float v, float* sred) {
    #pragma unroll
    for (int o = 16; o > 0; o >>= 1) v += __shfl_xor_sync(0xffffffffu, v, o);
    if ((threadIdx.x & 31) == 0) sred[threadIdx.x >> 5] = v;
    __syncthreads();
    return (sred[0] + sred[1]) + (sred[2] + sred[3]);
}

// ---------------- prep: normalize transition rows + prior ----------------
__global__ void prep_kernel(const float* __restrict__ trans,
                            const float* __restrict__ prior) {
    const int r = blockIdx.x;   // row (prev state)
    const int n = threadIdx.x;  // col (next state)
    __shared__ float sred[4];

    float v = fmaxf(trans[r * NN + n], EPSV);
    float rs = blk_sum128(v, sred);
    float tn = v / rs;
    g_trans[r * NN + n] = tn;
    g_transT[n * NN + r] = tn;

    if (r == 0) {
        float pv = fmaxf(prior[n], EPSV);
        __syncthreads();
        float ps = blk_sum128(pv, sred);
        g_prior[n] = pv / ps;
    }
}

// ---------------- expem: E = exp(log_emission), full-chip elementwise ----------------
__global__ void expem_kernel(const float* __restrict__ em) {
    const size_t i = (size_t)blockIdx.x * blockDim.x + threadIdx.x;
    const float4* src = (const float4*)em;
    float4* dst = (float4*)g_E;
    float4 v = src[i];
    v.x = __expf(v.x); v.y = __expf(v.y); v.z = __expf(v.z); v.w = __expf(v.w);
    dst[i] = v;
}

// ---------------- fused forward + backward: 2 sequences per CTA ----------------
__global__ void __launch_bounds__(2 * NN, 1)
trellis_kernel(float* __restrict__ out) {
    const int half = threadIdx.x >> 7;        // 0 or 1
    const int n = threadIdx.x & (NN - 1);     // state
    const int b = blockIdx.x * 2 + half;      // sequence
    const int barid = 1 + half;

    __shared__ ulonglong2 sh[2][2][NN / 4];   // [half][buf][vec]

    // register cache: forward uses columns of g_trans, backward reuses for rows of g_transT
    unsigned long long M2[NN / 2];
    #pragma unroll
    for (int k = 0; k < NN / 2; k++)
        M2[k] = pack2(g_trans[(2 * k) * NN + n], g_trans[(2 * k + 1) * NN + n]);

    const float* Eb = g_E + (size_t)b * TT * NN;
    float* Wb = g_W + (size_t)b * TT * NN;
    float* Vb = g_V + (size_t)b * TT * NN;
    float* outb = out + (size_t)b * TT * NN;

    // ---------- forward ----------
    float w = g_prior[n] * Eb[n];
    Wb[n] = w;

    float E_t = Eb[NN + n];  // exp(em) for t=1
    for (int t = 1; t < TT; t++) {
        const int buf = t & 1;
        float* shf = (float*)sh[half][buf];
        shf[n] = w;
        asm volatile("bar.sync %0, %1;" :: "r"(barid), "r"(2 * NN >> 1) : "memory");

        float E_next = (t + 1 < TT) ? Eb[(t + 1) * NN + n] : 0.f;  // prefetch
        float s0 = shf[0];
        float ip = inv_pin_of(s0);  // ALU-pipe, overlaps the dot

        const ulonglong2* sp = sh[half][buf];
        unsigned long long a0 = 0ull, a1 = 0ull, a2 = 0ull, a3 = 0ull;
        #pragma unroll
        for (int k = 0; k < NN / 4; k += 2) {
            ulonglong2 u0 = sp[k];
            ulonglong2 u1 = sp[k + 1];
            a0 = fma2(u0.x, M2[2 * k + 0], a0);
            a1 = fma2(u0.y, M2[2 * k + 1], a1);
            a2 = fma2(u1.x, M2[2 * k + 2], a2);
            a3 = fma2(u1.y, M2[2 * k + 3], a3);
        }
        float2 f0 = unpack2(a0), f1 = unpack2(a1), f2 = unpack2(a2), f3 = unpack2(a3);
        float v = ((f0.x + f0.y) + (f1.x + f1.y)) + ((f2.x + f2.y) + (f3.x + f3.y));

        float vh = v * ip;           // exact power-of-2 scale
        Vb[t * NN + n] = vh;
        w = E_t * vh;
        Wb[t * NN + n] = w;
        E_t = E_next;
    }

    // ---------- reload register cache with rows of trans (transposed layout) ----------
    #pragma unroll
    for (int k = 0; k < NN / 2; k++)
        M2[k] = pack2(g_transT[(2 * k) * NN + n], g_transT[(2 * k + 1) * NN + n]);

    // ---------- backward ----------
    float p = Wb[(TT - 1) * NN + n];  // unnormalized final softmax numerator
    outb[(TT - 1) * NN + n] = p;

    float rv = __frcp_rn(Vb[(TT - 1) * NN + n]);  // 1/vh_{t+1} for t=TT-2
    float w_t = Wb[(TT - 2) * NN + n];

    for (int t = TT - 2; t >= 0; t--) {
        const int buf = t & 1;
        float* shf = (float*)sh[half][buf];
        float q = p * rv;
        shf[n] = q;
        asm volatile("bar.sync %0, %1;" :: "r"(barid), "r"(2 * NN >> 1) : "memory");

        // prefetch next iteration's trellis values + precompute its reciprocal
        float v_pref = (t > 0) ? Vb[t * NN + n] : 1.f;
        float w_pref = (t > 0) ? Wb[(t - 1) * NN + n] : 0.f;
        float rv_next = __frcp_rn(v_pref);  // off critical chain

        float q0 = shf[0];
        float ip = inv_pin_of(q0);

        const ulonglong2* sp = sh[half][buf];
        unsigned long long a0 = 0ull, a1 = 0ull, a2 = 0ull, a3 = 0ull;
        #pragma unroll
        for (int k = 0; k < NN / 4; k += 2) {
            ulonglong2 u0 = sp[k];
            ulonglong2 u1 = sp[k + 1];
            a0 = fma2(u0.x, M2[2 * k + 0], a0);
            a1 = fma2(u0.y, M2[2 * k + 1], a1);
            a2 = fma2(u1.x, M2[2 * k + 2], a2);
            a3 = fma2(u1.y, M2[2 * k + 3], a3);
        }
        float2 f0 = unpack2(a0), f1 = unpack2(a1), f2 = unpack2(a2), f3 = unpack2(a3);
        float acc = ((f0.x + f0.y) + (f1.x + f1.y)) + ((f2.x + f2.y) + (f3.x + f3.y));

        p = w_t * acc * ip;
        outb[t * NN + n] = p;
        rv = rv_next;
        w_t = w_pref;
    }
}

// ---------------- final row normalization (full-chip parallel) ----------------
__global__ void norm_kernel(float* __restrict__ out) {
    const int wid = threadIdx.x >> 5;
    const int lane = threadIdx.x & 31;
    const size_t row = (size_t)blockIdx.x * 4 + wid;  // row over B*T
    float4* p = (float4*)(out + row * NN);
    float4 v = p[lane];
    float s = (v.x + v.y) + (v.z + v.w);
    #pragma unroll
    for (int o = 16; o > 0; o >>= 1) s += __shfl_xor_sync(0xffffffffu, s, o);
    float inv = __fdividef(1.0f, s);
    v.x *= inv; v.y *= inv; v.z *= inv; v.w *= inv;
    p[lane] = v;
}

extern "C" void kernel_launch(void* const* d_in, const int* in_sizes, int n_in,
                              void* d_out, int out_size) {
    const float* trans = (const float*)d_in[0];  // (128,128)
    const float* em    = (const float*)d_in[1];  // (32,512,128)
    const float* prior = (const float*)d_in[2];  // (128,)
    float* out = (float*)d_out;                  // (32,512,128)

    prep_kernel<<<NN, NN>>>(trans, prior);
    expem_kernel<<<(BB * TT * NN) / (256 * 4), 256>>>(em);
    trellis_kernel<<<BB / 2, 2 * NN>>>(out);
    norm_kernel<<<BB * TT / 4, NN>>>(out);
}